// round 15
// baseline (speedup 1.0000x reference)
#include <cuda_runtime.h>
#include <cuda_bf16.h>
#include <cuda_fp16.h>
#include <cstdint>

#define BATCH 2
#define SEQ 2048
#define DMODEL 2048
#define NHEADS 16
#define HDIM 128
#define HHDIM 64

typedef unsigned long long ull;

// ---------------- scratch (device globals: no allocations allowed) -----------
__device__ float g_xq[BATCH * SEQ * NHEADS * HDIM];
__device__ float g_xk[BATCH * SEQ * NHEADS * HDIM];
__device__ float g_xv[BATCH * SEQ * NHEADS * HDIM];
__device__ float g_lambda;

// GEMM operands: fp16 hi + (lo * 2048)
__device__ __half g_xhi[BATCH * SEQ * DMODEL];
__device__ __half g_xlo[BATCH * SEQ * DMODEL];
__device__ __half g_ahi[BATCH * SEQ * DMODEL];
__device__ __half g_alo[BATCH * SEQ * DMODEL];
__device__ __half g_whi[4][DMODEL * DMODEL];   // q,k,v,o
__device__ __half g_wlo[4][DMODEL * DMODEL];

// flash operands (bf16 hi/lo, unscaled) — proven round-13 path
__device__ __nv_bfloat16 g_qhi[BATCH * SEQ * DMODEL];
__device__ __nv_bfloat16 g_qlo[BATCH * SEQ * DMODEL];
__device__ __nv_bfloat16 g_khi[BATCH * SEQ * DMODEL];
__device__ __nv_bfloat16 g_klo[BATCH * SEQ * DMODEL];
__device__ __nv_bfloat16 g_vhiT[BATCH * NHEADS * HDIM * SEQ];  // [bh][d][s]
__device__ __nv_bfloat16 g_vloT[BATCH * NHEADS * HDIM * SEQ];
__device__ float g_attn1[BATCH * NHEADS * SEQ * HDIM];         // [bh][s][d]
__device__ float g_attn2[BATCH * NHEADS * SEQ * HDIM];

// ---------------- helpers ----------------------------------------------------
__device__ __forceinline__ uint32_t smem_u32(const void* p) {
    uint32_t a;
    asm("{ .reg .u64 t; cvta.to.shared.u64 t, %1; cvt.u32.u64 %0, t; }" : "=r"(a) : "l"(p));
    return a;
}
__device__ __forceinline__ void ldsm4(uint32_t* r, uint32_t addr) {
    asm volatile("ldmatrix.sync.aligned.m8n8.x4.shared.b16 {%0,%1,%2,%3}, [%4];"
                 : "=r"(r[0]), "=r"(r[1]), "=r"(r[2]), "=r"(r[3]) : "r"(addr));
}
// fp32-accum bf16 mma
__device__ __forceinline__ void mma16816(float* c, const uint32_t* a,
                                         uint32_t b0, uint32_t b1) {
    asm volatile("mma.sync.aligned.m16n8k16.row.col.f32.bf16.bf16.f32 "
                 "{%0,%1,%2,%3}, {%4,%5,%6,%7}, {%8,%9}, {%0,%1,%2,%3};"
                 : "+f"(c[0]), "+f"(c[1]), "+f"(c[2]), "+f"(c[3])
                 : "r"(a[0]), "r"(a[1]), "r"(a[2]), "r"(a[3]), "r"(b0), "r"(b1));
}
// fp32-accum fp16 mma
__device__ __forceinline__ void mma16816hf(float* c, const uint32_t* a,
                                           uint32_t b0, uint32_t b1) {
    asm volatile("mma.sync.aligned.m16n8k16.row.col.f32.f16.f16.f32 "
                 "{%0,%1,%2,%3}, {%4,%5,%6,%7}, {%8,%9}, {%0,%1,%2,%3};"
                 : "+f"(c[0]), "+f"(c[1]), "+f"(c[2]), "+f"(c[3])
                 : "r"(a[0]), "r"(a[1]), "r"(a[2]), "r"(a[3]), "r"(b0), "r"(b1));
}
// fp16-accum fp16 mma (corrections)
__device__ __forceinline__ void mma16816h(uint32_t* c, const uint32_t* a,
                                          uint32_t b0, uint32_t b1) {
    asm volatile("mma.sync.aligned.m16n8k16.row.col.f16.f16.f16.f16 "
                 "{%0,%1}, {%2,%3,%4,%5}, {%6,%7}, {%0,%1};"
                 : "+r"(c[0]), "+r"(c[1])
                 : "r"(a[0]), "r"(a[1]), "r"(a[2]), "r"(a[3]), "r"(b0), "r"(b1));
}
__device__ __forceinline__ void cp16(uint32_t saddr, const void* g) {
    asm volatile("cp.async.cg.shared.global [%0], [%1], 16;" :: "r"(saddr), "l"(g));
}
__device__ __forceinline__ void cp_commit() { asm volatile("cp.async.commit_group;"); }
__device__ __forceinline__ void cp_wait1()  { asm volatile("cp.async.wait_group 1;" ::: "memory"); }
__device__ __forceinline__ void cp_wait0()  { asm volatile("cp.async.wait_group 0;" ::: "memory"); }
// bf16 packing (flash path)
__device__ __forceinline__ uint32_t packbf(float lo, float hi) {
    uint32_t r; asm("cvt.rn.bf16x2.f32 %0, %1, %2;" : "=r"(r) : "f"(hi), "f"(lo)); return r;
}
__device__ __forceinline__ float bflo(uint32_t v) { return __uint_as_float(v << 16); }
__device__ __forceinline__ float bfhi(uint32_t v) { return __uint_as_float(v & 0xffff0000u); }

// ---------------- fp16 hi / scaled-lo split ----------------------------------
#define LOSCALE 2048.0f
#define INV_LOSCALE (1.0f / 2048.0f)

__global__ void split_fp16(const float* __restrict__ src, __half* __restrict__ hi,
                           __half* __restrict__ lo, int n) {
    int i = (blockIdx.x * blockDim.x + threadIdx.x) * 4;
    if (i >= n) return;
    float4 v = *(const float4*)(src + i);
    __half h0 = __float2half_rn(v.x), h1 = __float2half_rn(v.y);
    __half h2 = __float2half_rn(v.z), h3 = __float2half_rn(v.w);
    __half l0 = __float2half_rn((v.x - __half2float(h0)) * LOSCALE);
    __half l1 = __float2half_rn((v.y - __half2float(h1)) * LOSCALE);
    __half l2 = __float2half_rn((v.z - __half2float(h2)) * LOSCALE);
    __half l3 = __float2half_rn((v.w - __half2float(h3)) * LOSCALE);
    __half2 hp0 = __halves2half2(h0, h1), hp1 = __halves2half2(h2, h3);
    __half2 lp0 = __halves2half2(l0, l1), lp1 = __halves2half2(l2, l3);
    *(uint2*)(hi + i) = make_uint2(*(uint32_t*)&hp0, *(uint32_t*)&hp1);
    *(uint2*)(lo + i) = make_uint2(*(uint32_t*)&lp0, *(uint32_t*)&lp1);
}

// ---------------- fp16 dual-accum HMMA GEMM ----------------------------------
// Y[4096, 2048] = A @ W^T.  Main product f32-accum; 2 corrections f16-accum.
// CTA tile 128(M) x 64(N), 8 warps (2M x 4N), warp tile 64x16. K chunk 32.
#define TSTR 80
#define ABUF (128 * TSTR)            // 10240
#define BBUF (64 * TSTR)             // 5120
#define OFF_ALO ABUF
#define OFF_BHI (2 * ABUF)
#define OFF_BLO (2 * ABUF + BBUF)
#define HSTG (2 * ABUF + 2 * BBUF)   // 30720
#define GEMM_SMEM (2 * HSTG)         // 61440
#define NCH (DMODEL / 32)

struct GemmB { const __half* bhi; const __half* blo; float* y; };

__global__ __launch_bounds__(256, 2)
void gemm_mma(const __half* __restrict__ Ahi, const __half* __restrict__ Alo,
              GemmB b0, GemmB b1, GemmB b2) {
    extern __shared__ char smem[];
    const uint32_t sb = smem_u32(smem);
    const int tid = threadIdx.x, wid = tid >> 5, lane = tid & 31;
    const int n0 = blockIdx.x * 64, m0 = blockIdx.y * 128;
    GemmB g = (blockIdx.z == 0) ? b0 : ((blockIdx.z == 1) ? b1 : b2);

    const __half* Ah = Ahi + (size_t)m0 * DMODEL;
    const __half* Al = Alo + (size_t)m0 * DMODEL;
    const __half* Bh = g.bhi + (size_t)n0 * DMODEL;
    const __half* Bl = g.blo + (size_t)n0 * DMODEL;

    // loaders: A 2 cp/thread per buf (rows 128, chunks 4); B 1 cp/thread per buf
    const int arow = tid >> 1, ach = (tid & 1) * 2;
    const int brow = tid >> 2, bch = tid & 3;

    float accf[4][2][4];
    uint32_t acch[4][2][2];
#pragma unroll
    for (int mt = 0; mt < 4; mt++)
#pragma unroll
        for (int nt = 0; nt < 2; nt++) {
#pragma unroll
            for (int j = 0; j < 4; j++) accf[mt][nt][j] = 0.f;
            acch[mt][nt][0] = 0u; acch[mt][nt][1] = 0u;
        }

    // prologue: chunk 0 -> stage 0
    {
#pragma unroll
        for (int i = 0; i < 2; i++) {
            cp16(sb + arow * TSTR + (ach + i) * 16, Ah + (size_t)arow * DMODEL + (ach + i) * 8);
            cp16(sb + OFF_ALO + arow * TSTR + (ach + i) * 16, Al + (size_t)arow * DMODEL + (ach + i) * 8);
        }
        cp16(sb + OFF_BHI + brow * TSTR + bch * 16, Bh + (size_t)brow * DMODEL + bch * 8);
        cp16(sb + OFF_BLO + brow * TSTR + bch * 16, Bl + (size_t)brow * DMODEL + bch * 8);
        cp_commit();
    }

    const int wm = wid >> 2, wn = wid & 3;
    const int lrow = (lane & 7) + ((lane >> 3) & 1) * 8;
    const int l16 = lane >> 4;

    for (int c = 0; c < NCH; c++) {
        if (c + 1 < NCH) {
            uint32_t stb = sb + ((c + 1) & 1) * HSTG;
            int k0 = (c + 1) * 32;
#pragma unroll
            for (int i = 0; i < 2; i++) {
                cp16(stb + arow * TSTR + (ach + i) * 16, Ah + (size_t)arow * DMODEL + k0 + (ach + i) * 8);
                cp16(stb + OFF_ALO + arow * TSTR + (ach + i) * 16, Al + (size_t)arow * DMODEL + k0 + (ach + i) * 8);
            }
            cp16(stb + OFF_BHI + brow * TSTR + bch * 16, Bh + (size_t)brow * DMODEL + k0 + bch * 8);
            cp16(stb + OFF_BLO + brow * TSTR + bch * 16, Bl + (size_t)brow * DMODEL + k0 + bch * 8);
            cp_commit();
            cp_wait1();
        } else {
            cp_wait0();
        }
        __syncthreads();

        const uint32_t stb = sb + (c & 1) * HSTG;
#pragma unroll
        for (int ks = 0; ks < 2; ks++) {
            const int ch = ks * 2 + l16;
            uint32_t bh4[4], bl4[4];
            {
                uint32_t off = (wn * 16 + lrow) * TSTR + ch * 16;
                ldsm4(bh4, stb + OFF_BHI + off);
                ldsm4(bl4, stb + OFF_BLO + off);
            }
#pragma unroll
            for (int mt = 0; mt < 4; mt++) {
                uint32_t ah[4], al[4];
                uint32_t off = (wm * 64 + mt * 16 + lrow) * TSTR + ch * 16;
                ldsm4(ah, stb + off);
                ldsm4(al, stb + OFF_ALO + off);
#pragma unroll
                for (int nt = 0; nt < 2; nt++) {
                    mma16816hf(accf[mt][nt], ah, bh4[nt], bh4[nt + 2]);     // hi*hi  (f32 acc)
                    mma16816h(acch[mt][nt], ah, bl4[nt], bl4[nt + 2]);      // hi*lo' (f16 acc)
                    mma16816h(acch[mt][nt], al, bh4[nt], bh4[nt + 2]);      // lo'*hi (f16 acc)
                }
            }
        }
        __syncthreads();
    }

    // epilogue: D = main + corr/2048
    const int erow = lane >> 2, ecol = (lane & 3) * 2;
#pragma unroll
    for (int mt = 0; mt < 4; mt++)
#pragma unroll
        for (int nt = 0; nt < 2; nt++) {
            int rg = m0 + wm * 64 + mt * 16 + erow;
            int cg = n0 + wn * 16 + nt * 8 + ecol;
            __half2 c01 = *reinterpret_cast<__half2*>(&acch[mt][nt][0]);
            __half2 c23 = *reinterpret_cast<__half2*>(&acch[mt][nt][1]);
            float2 f01 = __half22float2(c01);
            float2 f23 = __half22float2(c23);
            *(float2*)(g.y + (size_t)rg * DMODEL + cg) =
                make_float2(accf[mt][nt][0] + f01.x * INV_LOSCALE,
                            accf[mt][nt][1] + f01.y * INV_LOSCALE);
            *(float2*)(g.y + (size_t)(rg + 8) * DMODEL + cg) =
                make_float2(accf[mt][nt][2] + f23.x * INV_LOSCALE,
                            accf[mt][nt][3] + f23.y * INV_LOSCALE);
        }
}

// ---------------- fused RoPE + scale + bf16 split (Q and K) ------------------
__global__ void rope_split_kernel(const float* __restrict__ fc) {
    int idx = blockIdx.x * blockDim.x + threadIdx.x;
    const int NP = BATCH * SEQ * NHEADS * HHDIM;
    if (idx >= NP) return;
    const float* buf;
    __nv_bfloat16 *dhi, *dlo;
    float scale;
    if (blockIdx.y == 0) { buf = g_xq; dhi = g_qhi; dlo = g_qlo; scale = 0.125f; }
    else                 { buf = g_xk; dhi = g_khi; dlo = g_klo; scale = 1.0f; }
    int d2 = idx & 63;
    int h  = (idx >> 6) & 15;
    int s  = (idx >> 10) & 2047;
    int b  = idx >> 21;
    size_t base = ((size_t)((b * SEQ + s) * NHEADS + h) << 7) + d2 * 2;
    const float* p = buf + base;
    const float* f = fc + s * 256 + d2 * 4;
    float e = p[0], o = p[1];
    float e2 = (e * f[0] + o * f[1]) * scale;
    float o2 = (e * f[2] + o * f[3]) * scale;
    uint32_t hp = packbf(e2, o2);
    uint32_t lp = packbf(e2 - bflo(hp), o2 - bfhi(hp));
    *(uint32_t*)(dhi + base) = hp;
    *(uint32_t*)(dlo + base) = lp;
}

// ---------------- V transpose + split:  [b][s][h][d] -> [bh][d][s] -----------
__global__ void vsplitT_kernel() {
    __shared__ float tile[32][33];
    int bh = blockIdx.z, b = bh >> 4, h = bh & 15;
    int stile = blockIdx.x, dt = blockIdx.y;
    int t = threadIdx.x, tr = t >> 5, tc = t & 31;
#pragma unroll
    for (int i = 0; i < 4; i++) {
        int sl = tr + i * 8;
        tile[sl][tc] = g_xv[(size_t)((b * SEQ + stile * 32 + sl) * NHEADS + h) * HDIM + dt * 32 + tc];
    }
    __syncthreads();
#pragma unroll
    for (int i = 0; i < 4; i++) {
        int dl = tr + i * 8;
        float v = tile[tc][dl];
        size_t dst = (size_t)bh * (HDIM * SEQ) + (size_t)(dt * 32 + dl) * SEQ + stile * 32 + tc;
        __nv_bfloat16 hv = __float2bfloat16(v);
        g_vhiT[dst] = hv;
        g_vloT[dst] = __float2bfloat16(v - __bfloat162float(hv));
    }
}

// ---------------- lambda scalar ---------------------------------------------
__global__ void lambda_kernel(const float* __restrict__ lq1, const float* __restrict__ lk1,
                              const float* __restrict__ lq2, const float* __restrict__ lk2) {
    int t = threadIdx.x;
    float s1 = lq1[t] * lk1[t] + lq1[t + 32] * lk1[t + 32];
    float s2 = lq2[t] * lk2[t] + lq2[t + 32] * lk2[t + 32];
#pragma unroll
    for (int o = 16; o; o >>= 1) {
        s1 += __shfl_xor_sync(0xffffffffu, s1, o);
        s2 += __shfl_xor_sync(0xffffffffu, s2, o);
    }
    if (t == 0) g_lambda = expf(s1) - expf(s2) + 0.2f;
}

// ---------------- HMMA differential flash attention (round-13, proven) -------
#define FTSTR 144
#define KT_B (64 * FTSTR)
#define VT_B (128 * FTSTR)
#define FSTG (2 * KT_B + 2 * VT_B)
#define FLASH_SMEM (2 * FSTG)

#define FLASH_LOAD_TILE(kt, s) do {                                              \
    uint32_t stg_ = sb + (s) * FSTG;                                             \
    for (int i_ = 0; i_ < 2; i_++) {                                             \
        int t_ = tid + i_ * 256; int row_ = t_ >> 3, ch_ = t_ & 7;               \
        size_t src_ = (size_t)((kt) * 64 + row_) * 2048 + ch_ * 8;               \
        cp16(stg_ + row_ * FTSTR + ch_ * 16, Kh + src_);                         \
        cp16(stg_ + KT_B + row_ * FTSTR + ch_ * 16, Kl + src_);                  \
    }                                                                            \
    for (int i_ = 0; i_ < 4; i_++) {                                             \
        int t_ = tid + i_ * 256; int row_ = t_ >> 3, ch_ = t_ & 7;               \
        size_t src_ = (size_t)row_ * 2048 + (kt) * 64 + ch_ * 8;                 \
        cp16(stg_ + 2 * KT_B + row_ * FTSTR + ch_ * 16, Vh + src_);              \
        cp16(stg_ + 2 * KT_B + VT_B + row_ * FTSTR + ch_ * 16, Vl + src_);       \
    }                                                                            \
    cp_commit();                                                                 \
} while (0)

__global__ __launch_bounds__(256, 1)
void flash_hmma() {
    extern __shared__ char fsm[];
    const uint32_t sb = smem_u32(fsm);
    const int tid = threadIdx.x, wid = tid >> 5, lane = tid & 31;
    const int qb = blockIdx.x, bh = blockIdx.y, st = blockIdx.z;
    const int b = bh >> 4, h = bh & 15;
    const int ntiles = 2 * qb + 2;

    const size_t qkbase = (size_t)b * (SEQ * DMODEL) + (size_t)h * HDIM + st * 64;
    const __nv_bfloat16* Qh = g_qhi + qkbase;
    const __nv_bfloat16* Ql = g_qlo + qkbase;
    const __nv_bfloat16* Kh = g_khi + qkbase;
    const __nv_bfloat16* Kl = g_klo + qkbase;
    const __nv_bfloat16* Vh = g_vhiT + (size_t)bh * (HDIM * SEQ);
    const __nv_bfloat16* Vl = g_vloT + (size_t)bh * (HDIM * SEQ);
    float* Og = (st == 0 ? g_attn1 : g_attn2) + (size_t)bh * (SEQ * HDIM);

#pragma unroll
    for (int i = 0; i < 4; i++) {
        int t = tid + i * 256;
        int row = t >> 3, ch = t & 7;
        size_t src = (size_t)(qb * 128 + row) * 2048 + ch * 8;
        cp16(sb + 2 * KT_B + row * FTSTR + ch * 16, Qh + src);
        cp16(sb + 2 * KT_B + VT_B + row * FTSTR + ch * 16, Ql + src);
    }
    cp_commit();
    cp_wait0();
    __syncthreads();

    const int lrow = (lane & 7) + ((lane >> 3) & 1) * 8;
    const int l16 = lane >> 4;

    uint32_t qh[4][4], ql[4][4];
#pragma unroll
    for (int ks = 0; ks < 4; ks++) {
        uint32_t off = (wid * 16 + lrow) * FTSTR + (ks * 2 + l16) * 16;
        ldsm4(qh[ks], sb + 2 * KT_B + off);
        ldsm4(ql[ks], sb + 2 * KT_B + VT_B + off);
    }
    __syncthreads();

    FLASH_LOAD_TILE(0, 0);

    float m0 = -1e30f, m1 = -1e30f, l0 = 0.f, l1 = 0.f;
    float oacc[16][4];
#pragma unroll
    for (int t = 0; t < 16; t++)
#pragma unroll
        for (int j = 0; j < 4; j++) oacc[t][j] = 0.f;

    const int r0g = qb * 128 + wid * 16 + (lane >> 2);
    const int colb = 2 * (lane & 3);

    for (int kt = 0; kt < ntiles; kt++) {
        if (kt + 1 < ntiles) { FLASH_LOAD_TILE(kt + 1, (kt + 1) & 1); cp_wait1(); }
        else cp_wait0();
        __syncthreads();
        const uint32_t stg = sb + (kt & 1) * FSTG;

        float sacc[8][4];
#pragma unroll
        for (int j = 0; j < 8; j++)
#pragma unroll
            for (int k = 0; k < 4; k++) sacc[j][k] = 0.f;
#pragma unroll
        for (int ks = 0; ks < 4; ks++) {
            uint32_t kh[4][4], kl[4][4];
#pragma unroll
            for (int p = 0; p < 4; p++) {
                uint32_t off = (p * 16 + lrow) * FTSTR + (ks * 2 + l16) * 16;
                ldsm4(kh[p], stg + off);
                ldsm4(kl[p], stg + KT_B + off);
            }
#pragma unroll
            for (int p = 0; p < 4; p++)
#pragma unroll
                for (int od = 0; od < 2; od++) {
                    float* s = sacc[p * 2 + od];
                    mma16816(s, qh[ks], kh[p][od], kh[p][od + 2]);
                    mma16816(s, qh[ks], kl[p][od], kl[p][od + 2]);
                    mma16816(s, ql[ks], kh[p][od], kh[p][od + 2]);
                }
        }

        if (kt >= 2 * qb) {
            int cb = kt * 64 + colb;
#pragma unroll
            for (int j = 0; j < 8; j++) {
                int c0 = cb + j * 8;
                if (c0 > r0g)     sacc[j][0] = -1e30f;
                if (c0 + 1 > r0g) sacc[j][1] = -1e30f;
                if (c0 > r0g + 8)     sacc[j][2] = -1e30f;
                if (c0 + 1 > r0g + 8) sacc[j][3] = -1e30f;
            }
        }

        float mx0 = -1e30f, mx1 = -1e30f;
#pragma unroll
        for (int j = 0; j < 8; j++) {
            mx0 = fmaxf(mx0, fmaxf(sacc[j][0], sacc[j][1]));
            mx1 = fmaxf(mx1, fmaxf(sacc[j][2], sacc[j][3]));
        }
        mx0 = fmaxf(mx0, __shfl_xor_sync(0xffffffffu, mx0, 1));
        mx0 = fmaxf(mx0, __shfl_xor_sync(0xffffffffu, mx0, 2));
        mx1 = fmaxf(mx1, __shfl_xor_sync(0xffffffffu, mx1, 1));
        mx1 = fmaxf(mx1, __shfl_xor_sync(0xffffffffu, mx1, 2));
        float mn0 = fmaxf(m0, mx0), mn1 = fmaxf(m1, mx1);
        float cr0 = __expf(m0 - mn0), cr1 = __expf(m1 - mn1);
        float ps0 = 0.f, ps1 = 0.f;
#pragma unroll
        for (int j = 0; j < 8; j++) {
            sacc[j][0] = __expf(sacc[j][0] - mn0); ps0 += sacc[j][0];
            sacc[j][1] = __expf(sacc[j][1] - mn0); ps0 += sacc[j][1];
            sacc[j][2] = __expf(sacc[j][2] - mn1); ps1 += sacc[j][2];
            sacc[j][3] = __expf(sacc[j][3] - mn1); ps1 += sacc[j][3];
        }
        ps0 += __shfl_xor_sync(0xffffffffu, ps0, 1);
        ps0 += __shfl_xor_sync(0xffffffffu, ps0, 2);
        ps1 += __shfl_xor_sync(0xffffffffu, ps1, 1);
        ps1 += __shfl_xor_sync(0xffffffffu, ps1, 2);
        l0 = l0 * cr0 + ps0; l1 = l1 * cr1 + ps1;
        m0 = mn0; m1 = mn1;
#pragma unroll
        for (int t = 0; t < 16; t++) {
            oacc[t][0] *= cr0; oacc[t][1] *= cr0;
            oacc[t][2] *= cr1; oacc[t][3] *= cr1;
        }

        uint32_t phf[4][4], plf[4][4];
#pragma unroll
        for (int j2 = 0; j2 < 4; j2++) {
            float* ta = sacc[2 * j2];
            float* tb = sacc[2 * j2 + 1];
            phf[j2][0] = packbf(ta[0], ta[1]);
            phf[j2][1] = packbf(ta[2], ta[3]);
            phf[j2][2] = packbf(tb[0], tb[1]);
            phf[j2][3] = packbf(tb[2], tb[3]);
            plf[j2][0] = packbf(ta[0] - bflo(phf[j2][0]), ta[1] - bfhi(phf[j2][0]));
            plf[j2][1] = packbf(ta[2] - bflo(phf[j2][1]), ta[3] - bfhi(phf[j2][1]));
            plf[j2][2] = packbf(tb[0] - bflo(phf[j2][2]), tb[1] - bfhi(phf[j2][2]));
            plf[j2][3] = packbf(tb[2] - bflo(phf[j2][3]), tb[3] - bfhi(phf[j2][3]));
        }

#pragma unroll
        for (int ks = 0; ks < 4; ks++) {
            uint32_t vf[8][4];
#pragma unroll
            for (int p = 0; p < 8; p++)
                ldsm4(vf[p], stg + 2 * KT_B + (p * 16 + lrow) * FTSTR + (ks * 2 + l16) * 16);
#pragma unroll
            for (int p = 0; p < 8; p++)
#pragma unroll
                for (int od = 0; od < 2; od++) {
                    mma16816(oacc[p * 2 + od], phf[ks], vf[p][od], vf[p][od + 2]);
                    mma16816(oacc[p * 2 + od], plf[ks], vf[p][od], vf[p][od + 2]);
                }
#pragma unroll
            for (int p = 0; p < 8; p++)
                ldsm4(vf[p], stg + 2 * KT_B + VT_B + (p * 16 + lrow) * FTSTR + (ks * 2 + l16) * 16);
#pragma unroll
            for (int p = 0; p < 8; p++)
#pragma unroll
                for (int od = 0; od < 2; od++)
                    mma16816(oacc[p * 2 + od], phf[ks], vf[p][od], vf[p][od + 2]);
        }
        __syncthreads();
    }

    float i0 = 1.f / l0, i1 = 1.f / l1;
    float* orow0 = Og + (size_t)(qb * 128 + wid * 16 + (lane >> 2)) * HDIM;
    float* orow1 = orow0 + 8 * HDIM;
#pragma unroll
    for (int t = 0; t < 16; t++) {
        int col = t * 8 + colb;
        *(float2*)(orow0 + col) = make_float2(oacc[t][0] * i0, oacc[t][1] * i0);
        *(float2*)(orow1 + col) = make_float2(oacc[t][2] * i1, oacc[t][3] * i1);
    }
}

// ---------------- combine: diff + RMSNorm + subln + 0.8 + fp16 split ---------
__global__ void combine_kernel(const float* __restrict__ subln) {
    int row = blockIdx.x * 8 + (threadIdx.x >> 5);
    int lane = threadIdx.x & 31;
    size_t off = (size_t)row * HDIM + lane * 4;
    float lam = g_lambda;
    float4 x1 = *(const float4*)(g_attn1 + off);
    float4 x2 = *(const float4*)(g_attn2 + off);
    float v0 = x1.x - lam * x2.x;
    float v1 = x1.y - lam * x2.y;
    float v2 = x1.z - lam * x2.z;
    float v3 = x1.w - lam * x2.w;
    float ss = v0 * v0 + v1 * v1 + v2 * v2 + v3 * v3;
#pragma unroll
    for (int o = 16; o; o >>= 1) ss += __shfl_xor_sync(0xffffffffu, ss, o);
    float rms = rsqrtf(ss * (1.0f / 128.0f) + 1e-5f);
    const float4 sw = *(const float4*)(subln + lane * 4);
    v0 *= rms * sw.x * 0.8f;
    v1 *= rms * sw.y * 0.8f;
    v2 *= rms * sw.z * 0.8f;
    v3 *= rms * sw.w * 0.8f;
    __half h0 = __float2half_rn(v0), h1 = __float2half_rn(v1);
    __half h2 = __float2half_rn(v2), h3 = __float2half_rn(v3);
    __half l0 = __float2half_rn((v0 - __half2float(h0)) * LOSCALE);
    __half l1 = __float2half_rn((v1 - __half2float(h1)) * LOSCALE);
    __half l2 = __float2half_rn((v2 - __half2float(h2)) * LOSCALE);
    __half l3 = __float2half_rn((v3 - __half2float(h3)) * LOSCALE);
    __half2 hp0 = __halves2half2(h0, h1), hp1 = __halves2half2(h2, h3);
    __half2 lp0 = __halves2half2(l0, l1), lp1 = __halves2half2(l2, l3);
    *(uint2*)(g_ahi + off) = make_uint2(*(uint32_t*)&hp0, *(uint32_t*)&hp1);
    *(uint2*)(g_alo + off) = make_uint2(*(uint32_t*)&lp0, *(uint32_t*)&lp1);
}

// ---------------- launch -----------------------------------------------------
extern "C" void kernel_launch(void* const* d_in, const int* in_sizes, int n_in,
                              void* d_out, int out_size) {
    const float* x    = (const float*)d_in[0];
    const float* fc   = (const float*)d_in[1];
    const float* w_in[4] = {(const float*)d_in[2], (const float*)d_in[3],
                            (const float*)d_in[4], (const float*)d_in[5]};
    const float* lq1  = (const float*)d_in[6];
    const float* lk1  = (const float*)d_in[7];
    const float* lq2  = (const float*)d_in[8];
    const float* lk2  = (const float*)d_in[9];
    const float* subw = (const float*)d_in[10];
    float* out = (float*)d_out;

    float *xq_p, *xk_p, *xv_p;
    __half *xhi, *xlo, *ahi, *alo, *whi, *wlo;
    cudaGetSymbolAddress((void**)&xq_p, g_xq);
    cudaGetSymbolAddress((void**)&xk_p, g_xk);
    cudaGetSymbolAddress((void**)&xv_p, g_xv);
    cudaGetSymbolAddress((void**)&xhi, g_xhi);
    cudaGetSymbolAddress((void**)&xlo, g_xlo);
    cudaGetSymbolAddress((void**)&ahi, g_ahi);
    cudaGetSymbolAddress((void**)&alo, g_alo);
    cudaGetSymbolAddress((void**)&whi, g_whi);
    cudaGetSymbolAddress((void**)&wlo, g_wlo);

    const int NX = BATCH * SEQ * DMODEL;          // 8388608
    const int NW = DMODEL * DMODEL;               // 4194304
    const int NP = BATCH * SEQ * NHEADS * HHDIM;  // 4194304

    split_fp16<<<NX / 1024, 256>>>(x, xhi, xlo, NX);
    for (int w = 0; w < 4; w++)
        split_fp16<<<NW / 1024, 256>>>(w_in[w], whi + (size_t)w * NW, wlo + (size_t)w * NW, NW);

    cudaFuncSetAttribute(gemm_mma, cudaFuncAttributeMaxDynamicSharedMemorySize, GEMM_SMEM);
    {
        GemmB bq = {whi + 0 * (size_t)NW, wlo + 0 * (size_t)NW, xq_p};
        GemmB bk = {whi + 1 * (size_t)NW, wlo + 1 * (size_t)NW, xk_p};
        GemmB bv = {whi + 2 * (size_t)NW, wlo + 2 * (size_t)NW, xv_p};
        gemm_mma<<<dim3(DMODEL / 64, (BATCH * SEQ) / 128, 3), 256, GEMM_SMEM>>>(
            xhi, xlo, bq, bk, bv);
    }

    rope_split_kernel<<<dim3(NP / 256, 2), 256>>>(fc);
    vsplitT_kernel<<<dim3(SEQ / 32, HDIM / 32, BATCH * NHEADS), 256>>>();
    lambda_kernel<<<1, 32>>>(lq1, lk1, lq2, lk2);

    cudaFuncSetAttribute(flash_hmma, cudaFuncAttributeMaxDynamicSharedMemorySize, FLASH_SMEM);
    flash_hmma<<<dim3(SEQ / 128, BATCH * NHEADS, 2), 256, FLASH_SMEM>>>();

    combine_kernel<<<(BATCH * NHEADS * SEQ) / 8, 256>>>(subw);

    {
        GemmB bo = {whi + 3 * (size_t)NW, wlo + 3 * (size_t)NW, out};
        gemm_mma<<<dim3(DMODEL / 64, (BATCH * SEQ) / 128, 1), 256, GEMM_SMEM>>>(
            ahi, alo, bo, bo, bo);
    }
}